// round 14
// baseline (speedup 1.0000x reference)
#include <cuda_runtime.h>
#include <math.h>

#define N 1024
#define TH 32
#define TW 16
#define NTHR 256

// ---- shared memory layout (in floats) ----
// W2 relaid: [c][k2][tap*2+(k&1)] : float idx = c*64 + k2*8 + tap*2 + (k&1)
// W3 relaid: [k][o2][tap*2+(o&1)] : float idx = k*32 + o2*8 + tap*2 + (o&1)
#define OFF_W2 0
#define OFF_W3 512
#define OFF_B2 1024
#define OFF_B3 1040
#define OFF_W4 1048
#define OFF_B4 1056
#define OFF_MS 1088                    // [34][19] mask (646)
#define OFF_M2 (OFF_MS + 34*19)       // [33][19] spread mask m2 (627)
#define OFF_H1 2368                    // [8][34][19] scalar h1 (5168)
#define OFF_H2 (OFF_H1 + 8*34*19)     // [8][33][19] float2 channel-pair h2 (byte-8 aligned)
#define SMEM_FLOATS (OFF_H2 + 8*33*19*2)
#define SMEM_BYTES (SMEM_FLOATS * 4)

#define H1STR (34*19)
#define H2P (33*19)                    // stride between k2 planes, in float2 units
#define LSTR 19

typedef unsigned long long u64;

__device__ __forceinline__ u64 pk2(float lo, float hi) {
    u64 r; asm("mov.b64 %0, {%1, %2};" : "=l"(r) : "f"(lo), "f"(hi)); return r;
}
__device__ __forceinline__ void upk2(u64 v, float& lo, float& hi) {
    asm("mov.b64 {%0, %1}, %2;" : "=f"(lo), "=f"(hi) : "l"(v));
}
__device__ __forceinline__ u64 fma2(u64 a, u64 b, u64 c) {
    u64 d; asm("fma.rn.f32x2 %0, %1, %2, %3;" : "=l"(d) : "l"(a), "l"(b), "l"(c)); return d;
}
__device__ __forceinline__ u64 mul2(u64 a, u64 b) {
    u64 d; asm("mul.rn.f32x2 %0, %1, %2;" : "=l"(d) : "l"(a), "l"(b)); return d;
}
// packed prelu: 0.5(1+a)x + 0.5(1-a)|x| per half; k1d/k2d are duplicated constants
__device__ __forceinline__ u64 prelu2(u64 v, u64 k1d, u64 k2d) {
    u64 ab = v & 0x7FFFFFFF7FFFFFFFULL;
    return fma2(k1d, v, mul2(k2d, ab));
}
__device__ __forceinline__ u64 lds2(const float* p) {
    float2 t = *reinterpret_cast<const float2*>(p);
    return pk2(t.x, t.y);
}

__global__ void __launch_bounds__(NTHR, 3)
precond_fused_kernel(const float* __restrict__ x, const int* __restrict__ mask,
                     const float* __restrict__ w1, const float* __restrict__ b1,
                     const float* __restrict__ a1p,
                     const float* __restrict__ w2, const float* __restrict__ b2,
                     const float* __restrict__ a2p,
                     const float* __restrict__ w3, const float* __restrict__ b3,
                     const float* __restrict__ a3p,
                     const float* __restrict__ w4, const float* __restrict__ b4,
                     float* __restrict__ out)
{
    extern __shared__ float sm[];
    float2* h2f2 = reinterpret_cast<float2*>(sm + OFF_H2);
    const int tid = threadIdx.x;
    const int c0 = blockIdx.x * TW;
    const int r0 = blockIdx.y * TH;
    const int bb = blockIdx.z;

    const int rC  = tid & 31;          // 0..31 output row (consecutive lanes -> rows)
    const int jj0 = (tid >> 5) << 1;   // 0..14 output col pair

    float* outB = out + (size_t)bb * N * N;

    // Tiles strictly above the diagonal are identically zero.
    if (c0 > r0 + (TH - 1)) {
        *(float2*)(outB + (size_t)(r0 + rC) * N + (c0 + jj0)) = make_float2(0.f, 0.f);
        return;
    }

    // ---- stage weights into shared, permuted for LDS.128 tap-pair access ----
    #pragma unroll
    for (int i = tid; i < 512; i += NTHR) {
        // w2 idx: k*32 + c*4 + tap  -> [c][k2][tap*2 + (k&1)]
        int k = i >> 5, c = (i >> 2) & 7, tap = i & 3;
        sm[OFF_W2 + c * 64 + (k >> 1) * 8 + tap * 2 + (k & 1)] = w2[i];
        // w3 idx: o*64 + k*4 + tap  -> [k][o2][tap*2 + (o&1)]
        int o = i >> 6, k3 = (i >> 2) & 15, tap3 = i & 3;
        sm[OFF_W3 + k3 * 32 + (o >> 1) * 8 + tap3 * 2 + (o & 1)] = w3[i];
    }
    if (tid < 16) sm[OFF_B2 + tid] = b2[tid];
    if (tid < 8)  { sm[OFF_B3 + tid] = b3[tid]; sm[OFF_W4 + tid] = w4[tid]; }
    if (tid == 0) sm[OFF_B4] = b4[0];

    const float a1 = __ldg(a1p);
    const float a2 = __ldg(a2p);
    const float a3 = __ldg(a3p);

    float w1r[8], b1r[8];
    #pragma unroll
    for (int c = 0; c < 8; c++) { w1r[c] = __ldg(w1 + c); b1r[c] = __ldg(b1 + c); }

    // ---- Phase A: load halo, compute h1 (folded-mask prelu) into scalar smem ----
    // Explicit 3-site unroll: all global loads issued up front (MLP 6), no loop.
    const float* xb = x    + (size_t)bb * N * N;
    const int*   mb = mask + (size_t)bb * N * N;
    const float k1a = 0.5f * (1.f + a1), k2a = 0.5f * (1.f - a1);
    {
        float xs[3], ms[3];
        int   its[3];
        #pragma unroll
        for (int s = 0; s < 3; s++) {
            int it = tid + s * NTHR;
            its[s] = it;
            xs[s] = 0.f; ms[s] = 0.f;
            if (it < 34 * 19) {
                int lr = it / 19, lc = it % 19;
                int gi = r0 - 1 + lr, gj = c0 - 1 + lc;
                if (gi >= 0 && gi < N && gj >= 0 && gj < N) {
                    float xr = xb[gi * N + gj];
                    int   mr = mb[gi * N + gj];
                    ms[s] = (mr > 0) ? 1.f : 0.f;
                    xs[s] = (mr > 0) ? xr : 0.f;
                }
            }
        }
        #pragma unroll
        for (int s = 0; s < 3; s++) {
            if (its[s] < 34 * 19) {
                sm[OFF_MS + its[s]] = ms[s];
                float k1m = ms[s] * k1a, k2m = ms[s] * k2a;
                #pragma unroll
                for (int c = 0; c < 8; c++) {
                    float y = fmaf(w1r[c], xs[s], b1r[c]);
                    sm[OFF_H1 + c * H1STR + its[s]] = fmaf(k1m, y, k2m * fabsf(y));
                }
            }
        }
    }
    __syncthreads();

    // ---- Phase B: h2 = prelu(m2 * conv2(h1)); h1 from smem; k2 split in halves ----
    // 33 rows x 6 groups (width 3) = 198 items, one per thread.
    if (tid < 33 * 6) {
        int r = tid % 33, g = tid / 33;
        int lc0 = g * 3;
        int jp0 = c0 - 1 + lc0;
        u64 actd[3];                           // duplicated act mask {0,0} or {1,1}
        {
            float s0[4], s1[4];
            #pragma unroll
            for (int q = 0; q < 4; q++) {
                s0[q] = sm[OFF_MS +  r      * LSTR + lc0 + q];
                s1[q] = sm[OFF_MS + (r + 1) * LSTR + lc0 + q];
            }
            #pragma unroll
            for (int p = 0; p < 3; p++) {
                int jp = jp0 + p;
                bool valid = (jp >= 0) && (jp <= N - 2);   // h2 cols beyond: layer-3 padding
                bool act = valid && ((s0[p] + s0[p + 1] + s1[p] + s1[p + 1]) > 0.f);
                float af = act ? 1.f : 0.f;
                actd[p] = pk2(af, af);
                sm[OFF_M2 + r * LSTR + lc0 + p] = af;
            }
        }
        const float k1bs = 0.5f * (1.f + a2), k2bs = 0.5f * (1.f - a2);
        const u64 k1bd = pk2(k1bs, k1bs), k2bd = pk2(k2bs, k2bs);

        #pragma unroll 1
        for (int half = 0; half < 2; half++) {
            u64 acc2[3][4];                    // [p][k-pair within half]
            const float* bb2 = sm + OFF_B2 + half * 8;
            #pragma unroll
            for (int u = 0; u < 4; u++) {
                u64 bp = lds2(bb2 + 2 * u);
                acc2[0][u] = bp; acc2[1][u] = bp; acc2[2][u] = bp;
            }
            #pragma unroll 1
            for (int c = 0; c < 8; c++) {
                const float* h1c = sm + OFF_H1 + c * H1STR;
                u64 vv0[4], vv1[4];
                #pragma unroll
                for (int q = 0; q < 4; q++) {
                    float t0 = h1c[ r      * LSTR + lc0 + q];
                    float t1 = h1c[(r + 1) * LSTR + lc0 + q];
                    vv0[q] = pk2(t0, t0);
                    vv1[q] = pk2(t1, t1);
                }
                const ulonglong2* wc2 =
                    reinterpret_cast<const ulonglong2*>(sm + OFF_W2 + c * 64 + half * 32);
                #pragma unroll
                for (int u = 0; u < 4; u++) {
                    ulonglong2 wa = wc2[u * 2];      // {w00pair, w01pair}
                    ulonglong2 wb = wc2[u * 2 + 1];  // {w10pair, w11pair}
                    #pragma unroll
                    for (int p = 0; p < 3; p++) {
                        acc2[p][u] = fma2(vv0[p],     wa.x, acc2[p][u]);
                        acc2[p][u] = fma2(vv0[p + 1], wa.y, acc2[p][u]);
                        acc2[p][u] = fma2(vv1[p],     wb.x, acc2[p][u]);
                        acc2[p][u] = fma2(vv1[p + 1], wb.y, acc2[p][u]);
                    }
                }
            }
            // packed prelu + mask + direct u64 store
            #pragma unroll
            for (int p = 0; p < 3; p++) {
                u64* h2p = reinterpret_cast<u64*>(h2f2 + (half * 4) * H2P + r * LSTR + lc0 + p);
                #pragma unroll
                for (int u = 0; u < 4; u++) {
                    u64 hp = mul2(actd[p], prelu2(acc2[p][u], k1bd, k2bd));
                    h2p[u * H2P] = hp;
                }
            }
        }
    }
    __syncthreads();

    // ---- Phase C: h3 = prelu(m3 * conv3(h2)); layer 4; packed o-pairs ----
    // 32 rows x 8 col-pairs = 256 items: one per thread. Channel-pair v loads.
    {
        const int r = rC, j0 = jj0;
        // m2 masks loaded up front (in flight during the compute loop)
        float m20[3], m21[3];
        #pragma unroll
        for (int q = 0; q < 3; q++) {
            m20[q] = sm[OFF_M2 +  r      * LSTR + j0 + q];
            m21[q] = sm[OFF_M2 + (r + 1) * LSTR + j0 + q];
        }
        u64 acc2[2][4];                  // [p][o-pair]
        #pragma unroll
        for (int o2 = 0; o2 < 4; o2++) {
            u64 bpair = lds2(sm + OFF_B3 + 2 * o2);
            acc2[0][o2] = bpair;
            acc2[1][o2] = bpair;
        }

        #pragma unroll 1
        for (int k2 = 0; k2 < 8; k2++) {
            const float2* h2k = h2f2 + k2 * H2P;
            // one float2 load yields v for channels 2*k2 (a) and 2*k2+1 (b)
            u64 va0[3], va1[3], vb0[3], vb1[3];
            #pragma unroll
            for (int q = 0; q < 3; q++) {
                float2 f0 = h2k[ r      * LSTR + j0 + q];
                float2 f1 = h2k[(r + 1) * LSTR + j0 + q];
                va0[q] = pk2(f0.x, f0.x);
                vb0[q] = pk2(f0.y, f0.y);
                va1[q] = pk2(f1.x, f1.x);
                vb1[q] = pk2(f1.y, f1.y);
            }
            const ulonglong2* wva = reinterpret_cast<const ulonglong2*>(sm + OFF_W3 + (2 * k2) * 32);
            const ulonglong2* wvb = reinterpret_cast<const ulonglong2*>(sm + OFF_W3 + (2 * k2 + 1) * 32);
            #pragma unroll
            for (int o2 = 0; o2 < 4; o2++) {
                ulonglong2 wa01 = wva[o2 * 2];      // chan a: {w00,w01}
                ulonglong2 wa23 = wva[o2 * 2 + 1];  // chan a: {w10,w11}
                ulonglong2 wb01 = wvb[o2 * 2];      // chan b
                ulonglong2 wb23 = wvb[o2 * 2 + 1];
                #pragma unroll
                for (int p = 0; p < 2; p++) {
                    acc2[p][o2] = fma2(va0[p],     wa01.x, acc2[p][o2]);
                    acc2[p][o2] = fma2(va0[p + 1], wa01.y, acc2[p][o2]);
                    acc2[p][o2] = fma2(va1[p],     wa23.x, acc2[p][o2]);
                    acc2[p][o2] = fma2(va1[p + 1], wa23.y, acc2[p][o2]);
                    acc2[p][o2] = fma2(vb0[p],     wb01.x, acc2[p][o2]);
                    acc2[p][o2] = fma2(vb0[p + 1], wb01.y, acc2[p][o2]);
                    acc2[p][o2] = fma2(vb1[p],     wb23.x, acc2[p][o2]);
                    acc2[p][o2] = fma2(vb1[p + 1], wb23.y, acc2[p][o2]);
                }
            }
        }

        const float b4v = sm[OFF_B4];
        const float k1cs = 0.5f * (1.f + a3), k2cs = 0.5f * (1.f - a3);
        const u64 k1cd = pk2(k1cs, k1cs), k2cd = pk2(k2cs, k2cs);
        u64 w4d[4];
        #pragma unroll
        for (int o2 = 0; o2 < 4; o2++) w4d[o2] = lds2(sm + OFF_W4 + 2 * o2);
        const int gi = r0 + r;
        float res[2];
        #pragma unroll
        for (int p = 0; p < 2; p++) {
            bool actc = (m20[p] + m20[p + 1] + m21[p] + m21[p + 1]) > 0.f;
            // packed prelu + packed layer-4 dot, one lo+hi fold
            u64 o4d = 0;
            #pragma unroll
            for (int o2 = 0; o2 < 4; o2++) {
                u64 h3d = prelu2(acc2[p][o2], k1cd, k2cd);
                o4d = fma2(w4d[o2], h3d, o4d);
            }
            float ua, ub;
            upk2(o4d, ua, ub);
            float o4 = b4v + ua + ub;
            o4 = actc ? o4 : 0.f;
            int gj = c0 + j0 + p;
            if (gi < gj) {
                o4 = 0.f;
            } else if (gi == gj && actc) {
                o4 = fmaxf(o4, 0.f) + log1pf(expf(-fabsf(o4)));  // stable softplus
            }
            res[p] = o4;
        }
        *(float2*)(outB + (size_t)gi * N + (c0 + j0)) = make_float2(res[0], res[1]);
    }
}

extern "C" void kernel_launch(void* const* d_in, const int* in_sizes, int n_in,
                              void* d_out, int out_size)
{
    (void)in_sizes; (void)n_in; (void)out_size;
    const float* x    = (const float*)d_in[0];
    const int*   mask = (const int*)  d_in[1];
    const float* w1   = (const float*)d_in[2];
    const float* b1   = (const float*)d_in[3];
    const float* a1   = (const float*)d_in[4];
    const float* w2   = (const float*)d_in[5];
    const float* b2   = (const float*)d_in[6];
    const float* a2   = (const float*)d_in[7];
    const float* w3   = (const float*)d_in[8];
    const float* b3   = (const float*)d_in[9];
    const float* a3   = (const float*)d_in[10];
    const float* w4   = (const float*)d_in[11];
    const float* b4   = (const float*)d_in[12];
    float* out = (float*)d_out;

    cudaFuncSetAttribute(precond_fused_kernel,
                         cudaFuncAttributeMaxDynamicSharedMemorySize, SMEM_BYTES);

    dim3 grid(N / TW, N / TH, 2);
    precond_fused_kernel<<<grid, NTHR, SMEM_BYTES>>>(
        x, mask, w1, b1, a1, w2, b2, a2, w3, b3, a3, w4, b4, out);
}

// round 15
// speedup vs baseline: 1.0356x; 1.0356x over previous
#include <cuda_runtime.h>
#include <math.h>

#define N 1024
#define TH 32
#define TW 16
#define NTHR 256

// ---- shared memory layout (in floats) ----
// W2 relaid: [c][k2][tap*2+(k&1)] : float idx = c*64 + k2*8 + tap*2 + (k&1)
// W3 relaid: [k][o2][tap*2+(o&1)] : float idx = k*32 + o2*8 + tap*2 + (o&1)
#define OFF_W2 0
#define OFF_W3 512
#define OFF_B2 1024
#define OFF_B3 1040
#define OFF_W4 1048
#define OFF_B4 1056
#define OFF_MS 1088                    // [34][19] mask (646)
#define OFF_M2 (OFF_MS + 34*19)       // [33][19] spread mask m2 (627)
#define OFF_H1 2368                    // [8][34][19] scalar h1 (5168)
#define OFF_H2 (OFF_H1 + 8*34*19)     // [8][33][19] float2 channel-pair h2 (byte-8 aligned)
#define SMEM_FLOATS (OFF_H2 + 8*33*19*2)
#define SMEM_BYTES (SMEM_FLOATS * 4)

#define H1STR (34*19)
#define H2P (33*19)                    // stride between k2 planes, in float2 units
#define LSTR 19

typedef unsigned long long u64;

__device__ __forceinline__ u64 pk2(float lo, float hi) {
    u64 r; asm("mov.b64 %0, {%1, %2};" : "=l"(r) : "f"(lo), "f"(hi)); return r;
}
__device__ __forceinline__ void upk2(u64 v, float& lo, float& hi) {
    asm("mov.b64 {%0, %1}, %2;" : "=f"(lo), "=f"(hi) : "l"(v));
}
__device__ __forceinline__ u64 fma2(u64 a, u64 b, u64 c) {
    u64 d; asm("fma.rn.f32x2 %0, %1, %2, %3;" : "=l"(d) : "l"(a), "l"(b), "l"(c)); return d;
}
__device__ __forceinline__ u64 mul2(u64 a, u64 b) {
    u64 d; asm("mul.rn.f32x2 %0, %1, %2;" : "=l"(d) : "l"(a), "l"(b)); return d;
}
// packed prelu: 0.5(1+a)x + 0.5(1-a)|x| per half; k1d/k2d are duplicated constants
__device__ __forceinline__ u64 prelu2(u64 v, u64 k1d, u64 k2d) {
    u64 ab = v & 0x7FFFFFFF7FFFFFFFULL;
    return fma2(k1d, v, mul2(k2d, ab));
}
__device__ __forceinline__ u64 lds2(const float* p) {
    float2 t = *reinterpret_cast<const float2*>(p);
    return pk2(t.x, t.y);
}

__global__ void __launch_bounds__(NTHR, 3)
precond_fused_kernel(const float* __restrict__ x, const int* __restrict__ mask,
                     const float* __restrict__ w1, const float* __restrict__ b1,
                     const float* __restrict__ a1p,
                     const float* __restrict__ w2, const float* __restrict__ b2,
                     const float* __restrict__ a2p,
                     const float* __restrict__ w3, const float* __restrict__ b3,
                     const float* __restrict__ a3p,
                     const float* __restrict__ w4, const float* __restrict__ b4,
                     float* __restrict__ out)
{
    extern __shared__ float sm[];
    float2* h2f2 = reinterpret_cast<float2*>(sm + OFF_H2);
    const int tid = threadIdx.x;
    const int c0 = blockIdx.x * TW;
    const int r0 = blockIdx.y * TH;
    const int bb = blockIdx.z;

    const int rC  = tid & 31;          // 0..31 output row (consecutive lanes -> rows)
    const int jj0 = (tid >> 5) << 1;   // 0..14 output col pair

    float* outB = out + (size_t)bb * N * N;

    // Tiles strictly above the diagonal are identically zero.
    if (c0 > r0 + (TH - 1)) {
        *(float2*)(outB + (size_t)(r0 + rC) * N + (c0 + jj0)) = make_float2(0.f, 0.f);
        return;
    }

    // ---- stage weights into shared, permuted for LDS.128 tap-pair access ----
    #pragma unroll
    for (int i = tid; i < 512; i += NTHR) {
        // w2 idx: k*32 + c*4 + tap  -> [c][k2][tap*2 + (k&1)]
        int k = i >> 5, c = (i >> 2) & 7, tap = i & 3;
        sm[OFF_W2 + c * 64 + (k >> 1) * 8 + tap * 2 + (k & 1)] = w2[i];
        // w3 idx: o*64 + k*4 + tap  -> [k][o2][tap*2 + (o&1)]
        int o = i >> 6, k3 = (i >> 2) & 15, tap3 = i & 3;
        sm[OFF_W3 + k3 * 32 + (o >> 1) * 8 + tap3 * 2 + (o & 1)] = w3[i];
    }
    if (tid < 16) sm[OFF_B2 + tid] = b2[tid];
    if (tid < 8)  { sm[OFF_B3 + tid] = b3[tid]; sm[OFF_W4 + tid] = w4[tid]; }
    if (tid == 0) sm[OFF_B4] = b4[0];

    const float a1 = __ldg(a1p);
    const float a2 = __ldg(a2p);
    const float a3 = __ldg(a3p);

    float w1r[8], b1r[8];
    #pragma unroll
    for (int c = 0; c < 8; c++) { w1r[c] = __ldg(w1 + c); b1r[c] = __ldg(b1 + c); }

    // ---- Phase A: load halo, compute h1 (folded-mask prelu) into scalar smem ----
    const float* xb = x    + (size_t)bb * N * N;
    const int*   mb = mask + (size_t)bb * N * N;
    const float k1a = 0.5f * (1.f + a1), k2a = 0.5f * (1.f - a1);
    for (int it = tid; it < 34 * 19; it += NTHR) {
        int lr = it / 19, lc = it % 19;
        int gi = r0 - 1 + lr, gj = c0 - 1 + lc;
        float xv = 0.f, mv = 0.f;
        if (gi >= 0 && gi < N && gj >= 0 && gj < N) {
            float xr = xb[gi * N + gj];
            int   mr = mb[gi * N + gj];
            mv = (mr > 0) ? 1.f : 0.f;
            xv = (mr > 0) ? xr : 0.f;
        }
        sm[OFF_MS + it] = mv;
        float k1m = mv * k1a, k2m = mv * k2a;   // per-site constants, reused over 8 channels
        #pragma unroll
        for (int c = 0; c < 8; c++) {
            float y = fmaf(w1r[c], xv, b1r[c]);
            sm[OFF_H1 + c * H1STR + it] = fmaf(k1m, y, k2m * fabsf(y));
        }
    }
    __syncthreads();

    // ---- Phase B: h2 = prelu(m2 * conv2(h1)); h1 from smem; k2 split in halves ----
    // 33 rows x 6 groups (width 3) = 198 items, one per thread.
    if (tid < 33 * 6) {
        int r = tid % 33, g = tid / 33;
        int lc0 = g * 3;
        int jp0 = c0 - 1 + lc0;
        u64 actd[3];                           // duplicated act mask {0,0} or {1,1}
        {
            float s0[4], s1[4];
            #pragma unroll
            for (int q = 0; q < 4; q++) {
                s0[q] = sm[OFF_MS +  r      * LSTR + lc0 + q];
                s1[q] = sm[OFF_MS + (r + 1) * LSTR + lc0 + q];
            }
            #pragma unroll
            for (int p = 0; p < 3; p++) {
                int jp = jp0 + p;
                bool valid = (jp >= 0) && (jp <= N - 2);   // h2 cols beyond: layer-3 padding
                bool act = valid && ((s0[p] + s0[p + 1] + s1[p] + s1[p + 1]) > 0.f);
                float af = act ? 1.f : 0.f;
                actd[p] = pk2(af, af);
                sm[OFF_M2 + r * LSTR + lc0 + p] = af;
            }
        }
        const float k1bs = 0.5f * (1.f + a2), k2bs = 0.5f * (1.f - a2);
        const u64 k1bd = pk2(k1bs, k1bs), k2bd = pk2(k2bs, k2bs);

        #pragma unroll 1
        for (int half = 0; half < 2; half++) {
            u64 acc2[3][4];                    // [p][k-pair within half]
            const float* bb2 = sm + OFF_B2 + half * 8;
            #pragma unroll
            for (int u = 0; u < 4; u++) {
                u64 bp = lds2(bb2 + 2 * u);
                acc2[0][u] = bp; acc2[1][u] = bp; acc2[2][u] = bp;
            }
            #pragma unroll 1
            for (int c = 0; c < 8; c++) {
                const float* h1c = sm + OFF_H1 + c * H1STR;
                u64 vv0[4], vv1[4];
                #pragma unroll
                for (int q = 0; q < 4; q++) {
                    float t0 = h1c[ r      * LSTR + lc0 + q];
                    float t1 = h1c[(r + 1) * LSTR + lc0 + q];
                    vv0[q] = pk2(t0, t0);
                    vv1[q] = pk2(t1, t1);
                }
                const ulonglong2* wc2 =
                    reinterpret_cast<const ulonglong2*>(sm + OFF_W2 + c * 64 + half * 32);
                #pragma unroll
                for (int u = 0; u < 4; u++) {
                    ulonglong2 wa = wc2[u * 2];      // {w00pair, w01pair}
                    ulonglong2 wb = wc2[u * 2 + 1];  // {w10pair, w11pair}
                    #pragma unroll
                    for (int p = 0; p < 3; p++) {
                        acc2[p][u] = fma2(vv0[p],     wa.x, acc2[p][u]);
                        acc2[p][u] = fma2(vv0[p + 1], wa.y, acc2[p][u]);
                        acc2[p][u] = fma2(vv1[p],     wb.x, acc2[p][u]);
                        acc2[p][u] = fma2(vv1[p + 1], wb.y, acc2[p][u]);
                    }
                }
            }
            // packed prelu + mask + direct u64 store
            #pragma unroll
            for (int p = 0; p < 3; p++) {
                u64* h2p = reinterpret_cast<u64*>(h2f2 + (half * 4) * H2P + r * LSTR + lc0 + p);
                #pragma unroll
                for (int u = 0; u < 4; u++) {
                    u64 hp = mul2(actd[p], prelu2(acc2[p][u], k1bd, k2bd));
                    h2p[u * H2P] = hp;
                }
            }
        }
    }
    __syncthreads();

    // ---- Phase C: h3 = prelu(m3 * conv3(h2)); layer 4; packed o-pairs ----
    // 32 rows x 8 col-pairs = 256 items: one per thread. Channel-pair v loads.
    {
        const int r = rC, j0 = jj0;
        u64 acc2[2][4];                  // [p][o-pair]
        #pragma unroll
        for (int o2 = 0; o2 < 4; o2++) {
            u64 bpair = lds2(sm + OFF_B3 + 2 * o2);
            acc2[0][o2] = bpair;
            acc2[1][o2] = bpair;
        }

        #pragma unroll 1
        for (int k2 = 0; k2 < 8; k2++) {
            const float2* h2k = h2f2 + k2 * H2P;
            // one float2 load yields v for channels 2*k2 (a) and 2*k2+1 (b)
            u64 va0[3], va1[3], vb0[3], vb1[3];
            #pragma unroll
            for (int q = 0; q < 3; q++) {
                float2 f0 = h2k[ r      * LSTR + j0 + q];
                float2 f1 = h2k[(r + 1) * LSTR + j0 + q];
                va0[q] = pk2(f0.x, f0.x);
                vb0[q] = pk2(f0.y, f0.y);
                va1[q] = pk2(f1.x, f1.x);
                vb1[q] = pk2(f1.y, f1.y);
            }
            const ulonglong2* wva = reinterpret_cast<const ulonglong2*>(sm + OFF_W3 + (2 * k2) * 32);
            const ulonglong2* wvb = reinterpret_cast<const ulonglong2*>(sm + OFF_W3 + (2 * k2 + 1) * 32);
            #pragma unroll
            for (int o2 = 0; o2 < 4; o2++) {
                ulonglong2 wa01 = wva[o2 * 2];      // chan a: {w00,w01}
                ulonglong2 wa23 = wva[o2 * 2 + 1];  // chan a: {w10,w11}
                ulonglong2 wb01 = wvb[o2 * 2];      // chan b
                ulonglong2 wb23 = wvb[o2 * 2 + 1];
                #pragma unroll
                for (int p = 0; p < 2; p++) {
                    acc2[p][o2] = fma2(va0[p],     wa01.x, acc2[p][o2]);
                    acc2[p][o2] = fma2(va0[p + 1], wa01.y, acc2[p][o2]);
                    acc2[p][o2] = fma2(va1[p],     wa23.x, acc2[p][o2]);
                    acc2[p][o2] = fma2(va1[p + 1], wa23.y, acc2[p][o2]);
                    acc2[p][o2] = fma2(vb0[p],     wb01.x, acc2[p][o2]);
                    acc2[p][o2] = fma2(vb0[p + 1], wb01.y, acc2[p][o2]);
                    acc2[p][o2] = fma2(vb1[p],     wb23.x, acc2[p][o2]);
                    acc2[p][o2] = fma2(vb1[p + 1], wb23.y, acc2[p][o2]);
                }
            }
        }

        float m20[3], m21[3];
        #pragma unroll
        for (int q = 0; q < 3; q++) {
            m20[q] = sm[OFF_M2 +  r      * LSTR + j0 + q];
            m21[q] = sm[OFF_M2 + (r + 1) * LSTR + j0 + q];
        }
        const float b4v = sm[OFF_B4];
        const float k1cs = 0.5f * (1.f + a3), k2cs = 0.5f * (1.f - a3);
        const u64 k1cd = pk2(k1cs, k1cs), k2cd = pk2(k2cs, k2cs);
        u64 w4d[4];
        #pragma unroll
        for (int o2 = 0; o2 < 4; o2++) w4d[o2] = lds2(sm + OFF_W4 + 2 * o2);
        const int gi = r0 + r;
        float res[2];
        #pragma unroll
        for (int p = 0; p < 2; p++) {
            bool actc = (m20[p] + m20[p + 1] + m21[p] + m21[p + 1]) > 0.f;
            // packed prelu + packed layer-4 dot, one lo+hi fold
            u64 o4d = 0;
            #pragma unroll
            for (int o2 = 0; o2 < 4; o2++) {
                u64 h3d = prelu2(acc2[p][o2], k1cd, k2cd);
                o4d = fma2(w4d[o2], h3d, o4d);
            }
            float ua, ub;
            upk2(o4d, ua, ub);
            float o4 = b4v + ua + ub;
            o4 = actc ? o4 : 0.f;
            int gj = c0 + j0 + p;
            if (gi < gj) {
                o4 = 0.f;
            } else if (gi == gj && actc) {
                o4 = fmaxf(o4, 0.f) + log1pf(expf(-fabsf(o4)));  // stable softplus
            }
            res[p] = o4;
        }
        *(float2*)(outB + (size_t)gi * N + (c0 + j0)) = make_float2(res[0], res[1]);
    }
}

extern "C" void kernel_launch(void* const* d_in, const int* in_sizes, int n_in,
                              void* d_out, int out_size)
{
    (void)in_sizes; (void)n_in; (void)out_size;
    const float* x    = (const float*)d_in[0];
    const int*   mask = (const int*)  d_in[1];
    const float* w1   = (const float*)d_in[2];
    const float* b1   = (const float*)d_in[3];
    const float* a1   = (const float*)d_in[4];
    const float* w2   = (const float*)d_in[5];
    const float* b2   = (const float*)d_in[6];
    const float* a2   = (const float*)d_in[7];
    const float* w3   = (const float*)d_in[8];
    const float* b3   = (const float*)d_in[9];
    const float* a3   = (const float*)d_in[10];
    const float* w4   = (const float*)d_in[11];
    const float* b4   = (const float*)d_in[12];
    float* out = (float*)d_out;

    cudaFuncSetAttribute(precond_fused_kernel,
                         cudaFuncAttributeMaxDynamicSharedMemorySize, SMEM_BYTES);

    dim3 grid(N / TW, N / TH, 2);
    precond_fused_kernel<<<grid, NTHR, SMEM_BYTES>>>(
        x, mask, w1, b1, a1, w2, b2, a2, w3, b3, a3, w4, b4, out);
}